// round 5
// baseline (speedup 1.0000x reference)
#include <cuda_runtime.h>

#define NB          4
#define P1_PTS      8192
#define P2_PTS      8192
#define TPB         128
#define NSRC        8                        // sources per thread
#define SRC_PER_BLK (TPB * NSRC)             // 1024
#define TSPLIT      16
#define TILE        (P2_PTS / TSPLIT)        // 512 targets per block
#define NPAIR       (TILE / 2)               // 256
#define CHUNKS_PER_B (P1_PTS / SRC_PER_BLK)  // 8
#define NCHUNK      (NB * CHUNKS_PER_B)      // 32
#define NBLOCKS     (NCHUNK * TSPLIT)        // 512
#define NSRC_TOT    (NB * P1_PTS)            // 32768
#define NEG_INF     (-3.402823466e38f)

#define RED_TPB     256
#define RED_BLKS    (NSRC_TOT / RED_TPB)     // 128

__device__ float g_pmax[TSPLIT * NSRC_TOT];  // 2 MB
__device__ float g_sums[RED_BLKS];

__device__ __forceinline__ unsigned long long pack2(float a, float b) {
    unsigned long long r;
    asm("mov.b64 %0, {%1, %2};" : "=l"(r) : "f"(a), "f"(b));
    return r;
}
__device__ __forceinline__ unsigned long long ffma2(unsigned long long a,
                                                    unsigned long long b,
                                                    unsigned long long c) {
    unsigned long long d;
    asm("fma.rn.f32x2 %0, %1, %2, %3;" : "=l"(d) : "l"(a), "l"(b), "l"(c));
    return d;
}
__device__ __forceinline__ void unpack2(unsigned long long v, float& lo, float& hi) {
    asm("mov.b64 {%0, %1}, %2;" : "=f"(lo), "=f"(hi) : "l"(v));
}

__global__ __launch_bounds__(TPB, 5)
void chamfer_main(const float* __restrict__ src, const float* __restrict__ tgt) {
    // Pair-interleaved target tile: pair p -> [x0,x1, y0,y1, z0,z1, h0,h1]
    __shared__ float sh[TILE * 4];           // 8 KB

    const int tid   = threadIdx.x;
    const int chunk = blockIdx.x >> 4;       // 0..31
    const int split = blockIdx.x & 15;       // 0..15
    const int batch = chunk >> 3;            // 8 chunks per batch
    const int sbase = (chunk & 7) * SRC_PER_BLK;

    // ---- load & pack this block's 512-target slice ----
    const float* tb = tgt + ((long)batch * P2_PTS + (long)split * TILE) * 3;
    for (int j = tid; j < TILE; j += TPB) {
        float x = tb[j * 3 + 0];
        float y = tb[j * 3 + 1];
        float z = tb[j * 3 + 2];
        float h = -0.5f * (x * x + y * y + z * z);
        float* b = sh + (j >> 1) * 8;
        int hl = j & 1;
        b[0 + hl] = x;
        b[2 + hl] = y;
        b[4 + hl] = z;
        b[6 + hl] = h;
    }

    // ---- eight source points per thread ----
    unsigned long long X[NSRC], Y[NSRC], Z[NSRC];
    const float* sp = src + ((long)batch * P1_PTS + sbase + tid) * 3;
    #pragma unroll
    for (int s = 0; s < NSRC; s++) {
        float x = sp[s * TPB * 3 + 0];
        float y = sp[s * TPB * 3 + 1];
        float z = sp[s * TPB * 3 + 2];
        X[s] = pack2(x, x);
        Y[s] = pack2(y, y);
        Z[s] = pack2(z, z);
    }

    float acc[NSRC];
    #pragma unroll
    for (int s = 0; s < NSRC; s++) acc[s] = NEG_INF;

    __syncthreads();

    const unsigned shb = (unsigned)__cvta_generic_to_shared(sh);

    // ---- inner loop: 2 target-pairs (4 targets) x 8 sources = 32 evals/iter ----
    #pragma unroll 2
    for (int p = 0; p < NPAIR; p += 2) {
        unsigned a0 = shb + (unsigned)p * 32u;
        unsigned long long xA, yA, zA, hA, xB, yB, zB, hB;
        asm("ld.shared.v2.u64 {%0, %1}, [%2];" : "=l"(xA), "=l"(yA) : "r"(a0));
        asm("ld.shared.v2.u64 {%0, %1}, [%2];" : "=l"(zA), "=l"(hA) : "r"(a0 + 16u));
        asm("ld.shared.v2.u64 {%0, %1}, [%2];" : "=l"(xB), "=l"(yB) : "r"(a0 + 32u));
        asm("ld.shared.v2.u64 {%0, %1}, [%2];" : "=l"(zB), "=l"(hB) : "r"(a0 + 48u));

        #pragma unroll
        for (int s = 0; s < NSRC; s++) {
            // interleaved A/B chains: two independent 3-ffma2 chains
            unsigned long long tA = ffma2(Z[s], zA, hA);
            unsigned long long tB = ffma2(Z[s], zB, hB);
            tA = ffma2(Y[s], yA, tA);
            tB = ffma2(Y[s], yB, tB);
            tA = ffma2(X[s], xA, tA);
            tB = ffma2(X[s], xB, tB);
            float lA, hA2, lB, hB2;
            unpack2(tA, lA, hA2);
            unpack2(tB, lB, hB2);
            acc[s] = fmaxf(acc[s], fmaxf(fmaxf(lA, hA2), fmaxf(lB, hB2)));
        }
    }

    const int gsrc = batch * P1_PTS + sbase + tid;
    #pragma unroll
    for (int s = 0; s < NSRC; s++)
        g_pmax[split * NSRC_TOT + gsrc + s * TPB] = acc[s];
}

__global__ __launch_bounds__(RED_TPB)
void chamfer_reduce(const float* __restrict__ src) {
    __shared__ float red[RED_TPB];
    const int tid  = threadIdx.x;
    const int gsrc = blockIdx.x * RED_TPB + tid;

    float m = NEG_INF;
    #pragma unroll
    for (int s = 0; s < TSPLIT; s++)
        m = fmaxf(m, g_pmax[s * NSRC_TOT + gsrc]);

    const float* sp = src + (long)gsrc * 3;
    const float sx = sp[0], sy = sp[1], sz = sp[2];
    const float s2 = sx * sx + sy * sy + sz * sz;
    const float nn = fmaxf(0.0f, fmaf(-2.0f, m, s2));

    red[tid] = nn;
    __syncthreads();
    #pragma unroll
    for (int s = RED_TPB / 2; s > 0; s >>= 1) {
        if (tid < s) red[tid] += red[tid + s];
        __syncthreads();
    }
    if (tid == 0) g_sums[blockIdx.x] = red[0];
}

__global__ __launch_bounds__(RED_BLKS)
void chamfer_final(float* __restrict__ out) {
    __shared__ float red[RED_BLKS];
    const int tid = threadIdx.x;
    red[tid] = g_sums[tid];
    __syncthreads();
    #pragma unroll
    for (int s = RED_BLKS / 2; s > 0; s >>= 1) {
        if (tid < s) red[tid] += red[tid + s];
        __syncthreads();
    }
    if (tid == 0) out[0] = red[0] * (1.0f / (float)NB);
}

extern "C" void kernel_launch(void* const* d_in, const int* in_sizes, int n_in,
                              void* d_out, int out_size) {
    const float* src = (const float*)d_in[0];   // (4, 8192, 3) f32
    const float* tgt = (const float*)d_in[1];   // (4, 8192, 3) f32
    float* out = (float*)d_out;                  // scalar f32

    chamfer_main<<<NBLOCKS, TPB>>>(src, tgt);
    chamfer_reduce<<<RED_BLKS, RED_TPB>>>(src);
    chamfer_final<<<1, RED_BLKS>>>(out);
}

// round 6
// speedup vs baseline: 1.0213x; 1.0213x over previous
#include <cuda_runtime.h>

#define NB          4
#define P1_PTS      8192
#define P2_PTS      8192
#define TPB         128
#define NSRC        8                        // sources per thread
#define SRC_PER_BLK (TPB * NSRC)             // 1024
#define TSPLIT      16
#define TILE        (P2_PTS / TSPLIT)        // 512 targets per block
#define NPAIR       (TILE / 2)               // 256
#define CHUNKS_PER_B (P1_PTS / SRC_PER_BLK)  // 8
#define NCHUNK      (NB * CHUNKS_PER_B)      // 32
#define NBLOCKS     (NCHUNK * TSPLIT)        // 512
#define NSRC_TOT    (NB * P1_PTS)            // 32768
#define NEG_INF     (-3.402823466e38f)

#define RED_TPB     256
#define RED_BLKS    (NSRC_TOT / RED_TPB)     // 128

__device__ float g_pmax[TSPLIT * NSRC_TOT];  // 2 MB
__device__ float g_sums[RED_BLKS];

__device__ __forceinline__ unsigned long long pack2(float a, float b) {
    unsigned long long r;
    asm("mov.b64 %0, {%1, %2};" : "=l"(r) : "f"(a), "f"(b));
    return r;
}
__device__ __forceinline__ unsigned long long ffma2(unsigned long long a,
                                                    unsigned long long b,
                                                    unsigned long long c) {
    unsigned long long d;
    asm("fma.rn.f32x2 %0, %1, %2, %3;" : "=l"(d) : "l"(a), "l"(b), "l"(c));
    return d;
}
__device__ __forceinline__ void unpack2(unsigned long long v, float& lo, float& hi) {
    asm("mov.b64 {%0, %1}, %2;" : "=f"(lo), "=f"(hi) : "l"(v));
}

__global__ __launch_bounds__(TPB, 5)
void chamfer_main(const float* __restrict__ src, const float* __restrict__ tgt) {
    // Pair-interleaved target tile: pair p -> [x0,x1, y0,y1, z0,z1, h0,h1]
    __shared__ float sh[TILE * 4];           // 8 KB

    const int tid   = threadIdx.x;
    const int chunk = blockIdx.x >> 4;       // 0..31
    const int split = blockIdx.x & 15;       // 0..15
    const int batch = chunk >> 3;            // 8 chunks per batch
    const int sbase = (chunk & 7) * SRC_PER_BLK;

    // ---- load & pack this block's 512-target slice ----
    const float* tb = tgt + ((long)batch * P2_PTS + (long)split * TILE) * 3;
    for (int j = tid; j < TILE; j += TPB) {
        float x = tb[j * 3 + 0];
        float y = tb[j * 3 + 1];
        float z = tb[j * 3 + 2];
        float h = -0.5f * (x * x + y * y + z * z);
        float* b = sh + (j >> 1) * 8;
        int hl = j & 1;
        b[0 + hl] = x;
        b[2 + hl] = y;
        b[4 + hl] = z;
        b[6 + hl] = h;
    }

    // ---- eight source points per thread ----
    unsigned long long X[NSRC], Y[NSRC], Z[NSRC];
    const float* sp = src + ((long)batch * P1_PTS + sbase + tid) * 3;
    #pragma unroll
    for (int s = 0; s < NSRC; s++) {
        float x = sp[s * TPB * 3 + 0];
        float y = sp[s * TPB * 3 + 1];
        float z = sp[s * TPB * 3 + 2];
        X[s] = pack2(x, x);
        Y[s] = pack2(y, y);
        Z[s] = pack2(z, z);
    }

    float acc[NSRC];
    #pragma unroll
    for (int s = 0; s < NSRC; s++) acc[s] = NEG_INF;

    __syncthreads();

    const unsigned shb = (unsigned)__cvta_generic_to_shared(sh);

    // ---- inner loop: 1 target-pair x 8 sources, stage-ordered for operand reuse ----
    // Stage Z: 8 consecutive FFMA2 share (zP, hP) -> reuse cache -> rt=2
    // Stage Y: 8 consecutive FFMA2 share yP; Stage X: share xP.
    #pragma unroll 2
    for (int p = 0; p < NPAIR; p++) {
        unsigned a0 = shb + (unsigned)p * 32u;
        unsigned long long xP, yP, zP, hP;
        asm("ld.shared.v2.u64 {%0, %1}, [%2];" : "=l"(xP), "=l"(yP) : "r"(a0));
        asm("ld.shared.v2.u64 {%0, %1}, [%2];" : "=l"(zP), "=l"(hP) : "r"(a0 + 16u));

        unsigned long long t[NSRC];
        #pragma unroll
        for (int s = 0; s < NSRC; s++) t[s] = ffma2(Z[s], zP, hP);
        #pragma unroll
        for (int s = 0; s < NSRC; s++) t[s] = ffma2(Y[s], yP, t[s]);
        #pragma unroll
        for (int s = 0; s < NSRC; s++) t[s] = ffma2(X[s], xP, t[s]);
        #pragma unroll
        for (int s = 0; s < NSRC; s++) {
            float lo, hi;
            unpack2(t[s], lo, hi);
            acc[s] = fmaxf(acc[s], fmaxf(lo, hi));
        }
    }

    const int gsrc = batch * P1_PTS + sbase + tid;
    #pragma unroll
    for (int s = 0; s < NSRC; s++)
        g_pmax[split * NSRC_TOT + gsrc + s * TPB] = acc[s];
}

__global__ __launch_bounds__(RED_TPB)
void chamfer_reduce(const float* __restrict__ src) {
    __shared__ float red[RED_TPB];
    const int tid  = threadIdx.x;
    const int gsrc = blockIdx.x * RED_TPB + tid;

    float m = NEG_INF;
    #pragma unroll
    for (int s = 0; s < TSPLIT; s++)
        m = fmaxf(m, g_pmax[s * NSRC_TOT + gsrc]);

    const float* sp = src + (long)gsrc * 3;
    const float sx = sp[0], sy = sp[1], sz = sp[2];
    const float s2 = sx * sx + sy * sy + sz * sz;
    const float nn = fmaxf(0.0f, fmaf(-2.0f, m, s2));

    red[tid] = nn;
    __syncthreads();
    #pragma unroll
    for (int s = RED_TPB / 2; s > 0; s >>= 1) {
        if (tid < s) red[tid] += red[tid + s];
        __syncthreads();
    }
    if (tid == 0) g_sums[blockIdx.x] = red[0];
}

__global__ __launch_bounds__(RED_BLKS)
void chamfer_final(float* __restrict__ out) {
    __shared__ float red[RED_BLKS];
    const int tid = threadIdx.x;
    red[tid] = g_sums[tid];
    __syncthreads();
    #pragma unroll
    for (int s = RED_BLKS / 2; s > 0; s >>= 1) {
        if (tid < s) red[tid] += red[tid + s];
        __syncthreads();
    }
    if (tid == 0) out[0] = red[0] * (1.0f / (float)NB);
}

extern "C" void kernel_launch(void* const* d_in, const int* in_sizes, int n_in,
                              void* d_out, int out_size) {
    const float* src = (const float*)d_in[0];   // (4, 8192, 3) f32
    const float* tgt = (const float*)d_in[1];   // (4, 8192, 3) f32
    float* out = (float*)d_out;                  // scalar f32

    chamfer_main<<<NBLOCKS, TPB>>>(src, tgt);
    chamfer_reduce<<<RED_BLKS, RED_TPB>>>(src);
    chamfer_final<<<1, RED_BLKS>>>(out);
}